// round 2
// baseline (speedup 1.0000x reference)
#include <cuda_runtime.h>
#include <cstdint>

// ---------------------------------------------------------------------------
// Network_1760936591970: 256 -> 512 -> 512 -> 256 MLP with per-node activation
//   act(x) = a0*tanh(x)*sin(a1*x+a2) + a3*x + a4
// followed by row softmax (N=256). B = 65536 rows, all fp32.
//
// Strategy: split-tf32 (Dekker 2-split, 3 MMAs) mma.sync GEMM => fp32-class
// accuracy on tensor pipes. Fused bias+activation epilogue. Separate softmax.
// ---------------------------------------------------------------------------

#define BATCH 65536

// scratch: h1 (65536x512), h2 (65536x512); h3 (65536x256) reuses g_h1
__device__ float g_h1[BATCH * 512];
__device__ float g_h2[BATCH * 512];

#define BM 128
#define BN 128
#define BK 16
#define PM 136   // pitch so that frag LDS addr = 136*tg + m  -> bank (8*tg+g+m)%32, conflict-free
#define PN 136

__device__ __forceinline__ uint32_t cvt_tf32(float x) {
    uint32_t r;
    asm("cvt.rna.tf32.f32 %0, %1;" : "=r"(r) : "f"(x));
    return r;
}

__device__ __forceinline__ void split_tf32(float x, uint32_t& hi, uint32_t& lo) {
    hi = cvt_tf32(x);
    float h = __uint_as_float(hi);
    lo = cvt_tf32(x - h);   // x - h exact (Sterbenz); lo rounding adds ~2^-22 rel
}

__device__ __forceinline__ void mma8(float* c, const uint32_t* a, uint32_t b0, uint32_t b1) {
    asm volatile(
        "mma.sync.aligned.m16n8k8.row.col.f32.tf32.tf32.f32 "
        "{%0,%1,%2,%3},{%4,%5,%6,%7},{%8,%9},{%0,%1,%2,%3};"
        : "+f"(c[0]), "+f"(c[1]), "+f"(c[2]), "+f"(c[3])
        : "r"(a[0]), "r"(a[1]), "r"(a[2]), "r"(a[3]), "r"(b0), "r"(b1));
}

__device__ __forceinline__ float act_f(float x, const float* a) {
    return a[0] * tanhf(x) * sinf(a[1] * x + a[2]) + a[3] * x + a[4];
}

// C[M,N] = act(A[M,K] @ W[K,N] + bias), row-major everything.
// grid = (N/BN, M/BM), 256 threads (8 warps as 2 x 4).
__global__ void __launch_bounds__(256)
gemm_act_kernel(const float* __restrict__ A, const float* __restrict__ W,
                const float* __restrict__ bias, const float* __restrict__ actp,
                float* __restrict__ out, int N, int K)
{
    __shared__ uint32_t Ah[BK][PM];
    __shared__ uint32_t Al[BK][PM];
    __shared__ uint32_t Bh[BK][PN];
    __shared__ uint32_t Bl[BK][PN];

    const int tid  = threadIdx.x;
    const int lane = tid & 31;
    const int warp = tid >> 5;
    const int wm   = warp & 1;   // 0..1 -> warp rows 64
    const int wn   = warp >> 1;  // 0..3 -> warp cols 32
    const int g    = lane >> 2;  // 0..7
    const int tg   = lane & 3;   // 0..3

    const int m0 = blockIdx.y * BM;
    const int n0 = blockIdx.x * BN;

    float acc[4][4][4];
    #pragma unroll
    for (int i = 0; i < 4; i++)
        #pragma unroll
        for (int j = 0; j < 4; j++)
            #pragma unroll
            for (int c = 0; c < 4; c++)
                acc[i][j][c] = 0.f;

    // A tile load mapping: 64 rows/pass, 4 float4 per row (BK=16)
    const int a_m = tid >> 2;        // 0..63
    const int a_q = (tid & 3) * 4;   // k offset 0,4,8,12
    // W tile load mapping: 8 k-rows/pass, 32 float4 across 128 cols
    const int b_k  = tid >> 5;       // 0..7
    const int b_n4 = (tid & 31) * 4; // 0..124

    const int kIters = K / BK;
    for (int it = 0; it < kIters; it++) {
        const int k0 = it * BK;

        float4 av0 = *(const float4*)(A + (size_t)(m0 + a_m) * K + k0 + a_q);
        float4 av1 = *(const float4*)(A + (size_t)(m0 + a_m + 64) * K + k0 + a_q);
        float4 wv0 = *(const float4*)(W + (size_t)(k0 + b_k) * N + n0 + b_n4);
        float4 wv1 = *(const float4*)(W + (size_t)(k0 + b_k + 8) * N + n0 + b_n4);

        __syncthreads();  // previous iteration's readers done

        // A: store transposed with hi/lo split
        {
            uint32_t h, l;
            split_tf32(av0.x, h, l); Ah[a_q + 0][a_m] = h; Al[a_q + 0][a_m] = l;
            split_tf32(av0.y, h, l); Ah[a_q + 1][a_m] = h; Al[a_q + 1][a_m] = l;
            split_tf32(av0.z, h, l); Ah[a_q + 2][a_m] = h; Al[a_q + 2][a_m] = l;
            split_tf32(av0.w, h, l); Ah[a_q + 3][a_m] = h; Al[a_q + 3][a_m] = l;
            split_tf32(av1.x, h, l); Ah[a_q + 0][a_m + 64] = h; Al[a_q + 0][a_m + 64] = l;
            split_tf32(av1.y, h, l); Ah[a_q + 1][a_m + 64] = h; Al[a_q + 1][a_m + 64] = l;
            split_tf32(av1.z, h, l); Ah[a_q + 2][a_m + 64] = h; Al[a_q + 2][a_m + 64] = l;
            split_tf32(av1.w, h, l); Ah[a_q + 3][a_m + 64] = h; Al[a_q + 3][a_m + 64] = l;
        }
        // W: contiguous rows, vectorized store
        {
            uint4 hv, lv;
            split_tf32(wv0.x, hv.x, lv.x); split_tf32(wv0.y, hv.y, lv.y);
            split_tf32(wv0.z, hv.z, lv.z); split_tf32(wv0.w, hv.w, lv.w);
            *(uint4*)&Bh[b_k][b_n4] = hv;
            *(uint4*)&Bl[b_k][b_n4] = lv;
            split_tf32(wv1.x, hv.x, lv.x); split_tf32(wv1.y, hv.y, lv.y);
            split_tf32(wv1.z, hv.z, lv.z); split_tf32(wv1.w, hv.w, lv.w);
            *(uint4*)&Bh[b_k + 8][b_n4] = hv;
            *(uint4*)&Bl[b_k + 8][b_n4] = lv;
        }
        __syncthreads();

        #pragma unroll
        for (int kk = 0; kk < BK; kk += 8) {
            uint32_t ah[4][4], al[4][4];
            #pragma unroll
            for (int mi = 0; mi < 4; mi++) {
                const int m = wm * 64 + mi * 16 + g;
                ah[mi][0] = Ah[kk + tg][m];
                ah[mi][1] = Ah[kk + tg][m + 8];
                ah[mi][2] = Ah[kk + tg + 4][m];
                ah[mi][3] = Ah[kk + tg + 4][m + 8];
                al[mi][0] = Al[kk + tg][m];
                al[mi][1] = Al[kk + tg][m + 8];
                al[mi][2] = Al[kk + tg + 4][m];
                al[mi][3] = Al[kk + tg + 4][m + 8];
            }
            #pragma unroll
            for (int ni = 0; ni < 4; ni++) {
                const int n = wn * 32 + ni * 8 + g;
                const uint32_t bh0 = Bh[kk + tg][n];
                const uint32_t bh1 = Bh[kk + tg + 4][n];
                const uint32_t bl0 = Bl[kk + tg][n];
                const uint32_t bl1 = Bl[kk + tg + 4][n];
                #pragma unroll
                for (int mi = 0; mi < 4; mi++) {
                    mma8(acc[mi][ni], ah[mi], bh0, bh1);  // hi*hi
                    mma8(acc[mi][ni], al[mi], bh0, bh1);  // lo*hi
                    mma8(acc[mi][ni], ah[mi], bl0, bl1);  // hi*lo
                }
            }
        }
    }

    // Epilogue: bias + activation, fp32 out
    const int warp_m0 = m0 + wm * 64;
    const int warp_n0 = n0 + wn * 32;
    #pragma unroll
    for (int ni = 0; ni < 4; ni++) {
        const int col = warp_n0 + ni * 8 + 2 * tg;
        const float bia0 = bias[col];
        const float bia1 = bias[col + 1];
        float p0[5], p1[5];
        #pragma unroll
        for (int j = 0; j < 5; j++) {
            p0[j] = actp[col * 5 + j];
            p1[j] = actp[(col + 1) * 5 + j];
        }
        #pragma unroll
        for (int mi = 0; mi < 4; mi++) {
            const int r0 = warp_m0 + mi * 16 + g;
            float2 o;
            o.x = act_f(acc[mi][ni][0] + bia0, p0);
            o.y = act_f(acc[mi][ni][1] + bia1, p1);
            *(float2*)&out[(size_t)r0 * N + col] = o;
            o.x = act_f(acc[mi][ni][2] + bia0, p0);
            o.y = act_f(acc[mi][ni][3] + bia1, p1);
            *(float2*)&out[(size_t)(r0 + 8) * N + col] = o;
        }
    }
}

// Row softmax, N = 256. One warp per row, 8 rows per 256-thread block.
__global__ void __launch_bounds__(256)
softmax_kernel(const float* __restrict__ in, float* __restrict__ out)
{
    const int row  = blockIdx.x * 8 + (threadIdx.x >> 5);
    const int lane = threadIdx.x & 31;
    const float* p = in + (size_t)row * 256;

    float v[8];
    float mx = -3.4e38f;
    #pragma unroll
    for (int i = 0; i < 8; i++) {
        v[i] = p[lane + 32 * i];
        mx = fmaxf(mx, v[i]);
    }
    #pragma unroll
    for (int off = 16; off > 0; off >>= 1)
        mx = fmaxf(mx, __shfl_xor_sync(0xFFFFFFFFu, mx, off));

    float s = 0.f;
    #pragma unroll
    for (int i = 0; i < 8; i++) {
        v[i] = expf(v[i] - mx);
        s += v[i];
    }
    #pragma unroll
    for (int off = 16; off > 0; off >>= 1)
        s += __shfl_xor_sync(0xFFFFFFFFu, s, off);

    float* o = out + (size_t)row * 256;
    #pragma unroll
    for (int i = 0; i < 8; i++)
        o[lane + 32 * i] = v[i] / s;
}

extern "C" void kernel_launch(void* const* d_in, const int* in_sizes, int n_in,
                              void* d_out, int out_size)
{
    (void)in_sizes; (void)n_in; (void)out_size;
    const float* data = (const float*)d_in[0];
    const float* W1   = (const float*)d_in[1];
    const float* b1   = (const float*)d_in[2];
    const float* a1   = (const float*)d_in[3];
    const float* W2   = (const float*)d_in[4];
    const float* b2   = (const float*)d_in[5];
    const float* a2   = (const float*)d_in[6];
    const float* W3   = (const float*)d_in[7];
    const float* b3   = (const float*)d_in[8];
    const float* a3   = (const float*)d_in[9];
    float* out = (float*)d_out;

    void *h1p = nullptr, *h2p = nullptr;
    cudaGetSymbolAddress(&h1p, g_h1);
    cudaGetSymbolAddress(&h2p, g_h2);
    float* h1 = (float*)h1p;
    float* h2 = (float*)h2p;
    float* h3 = h1;  // reuse: h1 fully consumed before layer-3 writes

    dim3 blk(256);
    // layer 1: [B,256] @ [256,512]
    gemm_act_kernel<<<dim3(512 / BN, BATCH / BM), blk>>>(data, W1, b1, a1, h1, 512, 256);
    // layer 2: [B,512] @ [512,512]
    gemm_act_kernel<<<dim3(512 / BN, BATCH / BM), blk>>>(h1, W2, b2, a2, h2, 512, 512);
    // layer 3: [B,512] @ [512,256]
    gemm_act_kernel<<<dim3(256 / BN, BATCH / BM), blk>>>(h2, W3, b3, a3, h3, 256, 512);
    // softmax over rows of 256
    softmax_kernel<<<BATCH / 8, blk>>>(h3, out);
}